// round 7
// baseline (speedup 1.0000x reference)
#include <cuda_runtime.h>
#include <cuda_bf16.h>
#include <cstdint>

#define NPTS   64
#define NANGS  2016
#define NCOLS  300000
#define NSEG   8
#define LSEG   (NANGS / NSEG)   // 252
#define NBLK   8

typedef unsigned int u32;

// Build pipeline buffers (all __device__ — no allocation).
__device__ float g_M[NSEG * NPTS * NPTS];      // segment matrices
__device__ float g_P[4 * NPTS * NPTS];         // level-1 products
__device__ float g_Q[2 * NPTS * NPTS];         // level-2 products
__device__ float g_R[NPTS * NPTS];             // final R

// Grid barrier state (sense-reversing; g_cnt returns to 0 after each barrier,
// g_gen monotonically increments — behavior identical on every graph replay).
__device__ int      g_cnt = 0;
__device__ unsigned g_gen = 0;

__device__ __forceinline__ void grid_barrier() {
    __threadfence();
    __syncthreads();
    if (threadIdx.x == 0) {
        unsigned my = *(volatile unsigned*)&g_gen;
        if (atomicAdd(&g_cnt, 1) == NBLK - 1) {
            g_cnt = 0;
            __threadfence();
            *(volatile unsigned*)&g_gen = my + 1;
        } else {
            while (*(volatile unsigned*)&g_gen == my) { }
        }
        __threadfence();
    }
    __syncthreads();
}

__device__ __forceinline__ u32 smem_u32(const void* p) {
    u32 a;
    asm("{ .reg .u64 t; cvta.to.shared.u64 t, %1; cvt.u32.u64 %0, t; }"
        : "=r"(a) : "l"(p));
    return a;
}

// ---------------------------------------------------------------------------
// Product slice: C[:, jbase:jbase+NC] = A @ B[:, jbase:jbase+NC] (opt. mus row
// scale). As = A row-major (broadcast LDS in inner loop), Bs staged slice.
// ---------------------------------------------------------------------------
template <int NC>
__device__ __forceinline__ void prod_slice(
    float* As, float* Bs,
    const float* __restrict__ A, const float* __restrict__ B,
    float* __restrict__ C, int jbase, const float* __restrict__ mus)
{
    for (int idx = threadIdx.x; idx < NPTS * NPTS; idx += 256) As[idx] = A[idx];
    for (int idx = threadIdx.x; idx < NPTS * NC; idx += 256) {
        const int k = idx / NC, jl = idx % NC;
        Bs[idx] = B[k * NPTS + jbase + jl];
    }
    __syncthreads();

    const int jl  = threadIdx.x % NC;
    const int rq  = threadIdx.x / NC;
    constexpr int RPT = (NPTS * NC) / 256;   // rows per thread
    const int r0  = rq * RPT;

    float acc[RPT];
#pragma unroll
    for (int i = 0; i < RPT; i++) acc[i] = 0.0f;

#pragma unroll 4
    for (int k = 0; k < NPTS; k++) {
        const float b = Bs[k * NC + jl];
#pragma unroll
        for (int i = 0; i < RPT; i++)
            acc[i] = fmaf(As[(r0 + i) * NPTS + k], b, acc[i]);
    }

#pragma unroll
    for (int i = 0; i < RPT; i++) {
        float v = acc[i];
        if (mus) v *= mus[r0 + i];
        C[(r0 + i) * NPTS + jbase + jl] = v;
    }
    __syncthreads();   // before smem reuse next phase
}

// ---------------------------------------------------------------------------
// Fused build: 8 blocks. Phase 1 = segment matrices; phases 2-4 = product tree.
// R = diag(mus) * M7*...*M0.
// ---------------------------------------------------------------------------
__global__ void __launch_bounds__(256, 1)
build_fused_kernel(const float* __restrict__ angles, const float* __restrict__ mus) {
    __shared__ float2 cs[LSEG];
    __shared__ float  Seg[NPTS * NPTS];   // 16 KB (phase1 state, phase2+ = As)
    __shared__ float  Bs[NPTS * 32];      // 8 KB

    const int tid = threadIdx.x;
    const int s   = blockIdx.x;

    // ---- Phase 1: segment s ----
    const int i0 = s * LSEG;
    const int i1 = i0 + LSEG;
    for (int i = tid; i < LSEG; i += 256) {
        float sv, cv;
        __sincosf(angles[i0 + i], &sv, &cv);
        cs[i] = make_float2(cv, sv);
    }
    for (int idx = tid; idx < NPTS * NPTS; idx += 256)
        Seg[idx] = ((idx >> 6) == (idx & 63)) ? 1.0f : 0.0f;
    __syncthreads();

    if (tid < NPTS) {
        const int j = tid;
#pragma unroll 1
        for (int t = 0; t < NPTS - 1; t++) {
            const int gs   = t * (2 * NPTS - 1 - t) / 2;
            const int glen = NPTS - 1 - t;
            if (gs >= i1) break;
            if (gs + glen <= i0) continue;
            int lo = i0 - gs; if (lo < 0) lo = 0;
            int hi = i1 - gs; if (hi > glen) hi = glen;

            float rt = Seg[t * NPTS + j];
#pragma unroll 7
            for (int b = t + 1 + lo; b < t + 1 + hi; b++) {
                const float2 p  = cs[gs + (b - t - 1) - i0];
                const float  rb = Seg[b * NPTS + j];
                Seg[b * NPTS + j] = fmaf(p.y, rt, p.x * rb);
                rt = fmaf(p.x, rt, -(p.y * rb));
            }
            Seg[t * NPTS + j] = rt;
        }
    }
    __syncthreads();
    for (int idx = tid; idx < NPTS * NPTS; idx += 256)
        g_M[s * (NPTS * NPTS) + idx] = Seg[idx];

    grid_barrier();

    // ---- Phase 2: level-1 products P_p = M_{2p+1} @ M_{2p} (2 blocks/product)
    {
        const int p = s >> 1, h = s & 1;
        prod_slice<32>(Seg, Bs,
                       g_M + (2 * p + 1) * (NPTS * NPTS),
                       g_M + (2 * p) * (NPTS * NPTS),
                       g_P + p * (NPTS * NPTS), h * 32, nullptr);
    }
    grid_barrier();

    // ---- Phase 3: level-2 products Q_p = P_{2p+1} @ P_{2p} (4 blocks/product)
    {
        const int p = s >> 2, q = s & 3;
        prod_slice<16>(Seg, Bs,
                       g_P + (2 * p + 1) * (NPTS * NPTS),
                       g_P + (2 * p) * (NPTS * NPTS),
                       g_Q + p * (NPTS * NPTS), q * 16, nullptr);
    }
    grid_barrier();

    // ---- Phase 4: R = diag(mus) * (Q1 @ Q0) (8 blocks, 8 cols each)
    prod_slice<8>(Seg, Bs,
                  g_Q + (NPTS * NPTS), g_Q, g_R, s * 8, mus);
}

// ---------------------------------------------------------------------------
// GEMM: Y = R @ X via bf16 split-precision HMMA (3-term):
//   Y ~= Rhi@Xhi + Rhi@Xlo + Rlo@Xhi   (fp32 accumulate)
// Warp tile 64x16, ldmatrix.x4 A-frags, 2-deep X prefetch, 3 blocks/SM.
// ---------------------------------------------------------------------------
#define LDR 36

#define CVT_PACK(d, x1, x0) \
    asm("cvt.rn.bf16x2.f32 %0, %1, %2;" : "=r"(d) : "f"(x1), "f"(x0))

#define LDMX4(R0, R1, R2, R3, ADDR)                                            \
    asm volatile("ldmatrix.sync.aligned.m8n8.x4.shared.b16 {%0,%1,%2,%3}, [%4];" \
                 : "=r"(R0), "=r"(R1), "=r"(R2), "=r"(R3) : "r"(ADDR))

#define MMA_BF16(ACC, A0, A1, A2, A3, B0, B1)                                  \
    asm volatile(                                                              \
        "mma.sync.aligned.m16n8k16.row.col.f32.bf16.bf16.f32 "                 \
        "{%0,%1,%2,%3},{%4,%5,%6,%7},{%8,%9},{%0,%1,%2,%3};"                   \
        : "+f"(ACC[0]), "+f"(ACC[1]), "+f"(ACC[2]), "+f"(ACC[3])               \
        : "r"(A0), "r"(A1), "r"(A2), "r"(A3), "r"(B0), "r"(B1))

__global__ void __launch_bounds__(256, 3)
gemm_hmma_kernel(const float* __restrict__ X, float* __restrict__ Y) {
    __shared__ u32 RhiS[NPTS * LDR];
    __shared__ u32 RloS[NPTS * LDR];

    for (int idx = threadIdx.x; idx < NPTS * 32; idx += 256) {
        const int row = idx >> 5, kp = idx & 31;
        const float x0 = g_R[row * NPTS + 2 * kp];
        const float x1 = g_R[row * NPTS + 2 * kp + 1];
        u32 hh; CVT_PACK(hh, x1, x0);
        const float h0 = __uint_as_float(hh << 16);
        const float h1 = __uint_as_float(hh & 0xFFFF0000u);
        u32 ll; CVT_PACK(ll, x1 - h1, x0 - h0);
        RhiS[row * LDR + kp] = hh;
        RloS[row * LDR + kp] = ll;
    }
    __syncthreads();

    const int warp = threadIdx.x >> 5;
    const int lane = threadIdx.x & 31;
    const int g = lane >> 2;
    const int t = lane & 3;

    const long n0 = (long)blockIdx.x * 128 + warp * 16;
    if (n0 + 16 > NCOLS) return;

    const int r8   = lane & 7;
    const int selm = (lane >> 3) & 1;
    const int selk = (lane >> 4) & 1;
    const u32 laneoff = (u32)(((selm * 8 + r8) * LDR + selk * 4) * 4);
    const u32 ahibase = smem_u32(RhiS) + laneoff;
    const u32 alobase = smem_u32(RloS) + laneoff;

    float acc[4][2][4];
#pragma unroll
    for (int mt = 0; mt < 4; mt++)
#pragma unroll
        for (int nt = 0; nt < 2; nt++)
#pragma unroll
            for (int q = 0; q < 4; q++) acc[mt][nt][q] = 0.0f;

    const float* __restrict__ xb = X + n0 + g;
    float raw[2][8];

#define LOADK(BUF, KS)                                                         \
    do {                                                                       \
        const size_t o  = (size_t)((KS)*16 + 2 * t) * NCOLS;                   \
        const size_t o8 = o + (size_t)8 * NCOLS;                               \
        raw[BUF][0] = xb[o];      raw[BUF][1] = xb[o + NCOLS];                 \
        raw[BUF][2] = xb[o8];     raw[BUF][3] = xb[o8 + NCOLS];                \
        raw[BUF][4] = xb[o + 8];  raw[BUF][5] = xb[o + NCOLS + 8];             \
        raw[BUF][6] = xb[o8 + 8]; raw[BUF][7] = xb[o8 + NCOLS + 8];            \
    } while (0)

    LOADK(0, 0);
    LOADK(1, 1);

#pragma unroll
    for (int ks = 0; ks < 4; ks++) {
        const int cur = ks & 1;

        u32 bhi[2][2], blo[2][2];
#pragma unroll
        for (int nt = 0; nt < 2; nt++) {
#pragma unroll
            for (int h2 = 0; h2 < 2; h2++) {
                const float x0 = raw[cur][nt * 4 + h2 * 2];
                const float x1 = raw[cur][nt * 4 + h2 * 2 + 1];
                u32 hh; CVT_PACK(hh, x1, x0);
                const float h0 = __uint_as_float(hh << 16);
                const float h1 = __uint_as_float(hh & 0xFFFF0000u);
                u32 ll; CVT_PACK(ll, x1 - h1, x0 - h0);
                bhi[nt][h2] = hh;
                blo[nt][h2] = ll;
            }
        }

        if (ks + 2 < 4) LOADK(cur, ks + 2);

#pragma unroll
        for (int mt = 0; mt < 4; mt++) {
            const u32 off = (u32)(mt * 16 * LDR * 4 + ks * 32);
            u32 ah0, ah1, ah2, ah3, al0, al1, al2, al3;
            LDMX4(ah0, ah1, ah2, ah3, ahibase + off);
            LDMX4(al0, al1, al2, al3, alobase + off);
#pragma unroll
            for (int nt = 0; nt < 2; nt++) {
                MMA_BF16(acc[mt][nt], ah0, ah1, ah2, ah3, bhi[nt][0], bhi[nt][1]);
                MMA_BF16(acc[mt][nt], ah0, ah1, ah2, ah3, blo[nt][0], blo[nt][1]);
                MMA_BF16(acc[mt][nt], al0, al1, al2, al3, bhi[nt][0], bhi[nt][1]);
            }
        }
    }
#undef LOADK

#pragma unroll
    for (int mt = 0; mt < 4; mt++) {
        const int r0 = mt * 16 + g;
#pragma unroll
        for (int nt = 0; nt < 2; nt++) {
            const long col = n0 + 8 * nt + 2 * t;
            *reinterpret_cast<float2*>(Y + (size_t)r0 * NCOLS + col) =
                make_float2(acc[mt][nt][0], acc[mt][nt][1]);
            *reinterpret_cast<float2*>(Y + (size_t)(r0 + 8) * NCOLS + col) =
                make_float2(acc[mt][nt][2], acc[mt][nt][3]);
        }
    }
}

// ---------------------------------------------------------------------------
// Inputs (metadata order): X (64*300000 f32), angles (2016 f32), mus (64 f32).
// ---------------------------------------------------------------------------
extern "C" void kernel_launch(void* const* d_in, const int* in_sizes, int n_in,
                              void* d_out, int out_size) {
    const float* X      = (const float*)d_in[0];
    const float* angles = (const float*)d_in[1];
    const float* mus    = (const float*)d_in[2];
    float* Y            = (float*)d_out;

    build_fused_kernel<<<NBLK, 256>>>(angles, mus);

    const int blocks = (NCOLS + 127) / 128;   // 2344
    gemm_hmma_kernel<<<blocks, 256>>>(X, Y);
}